// round 14
// baseline (speedup 1.0000x reference)
#include <cuda_runtime.h>
#include <math.h>
#include <stdint.h>

#define B 4
#define S 4096
#define F 128
#define GAMMA 0.96875f
#define NTILE 64
#define TPB 256
#define NQTILES ((B*S)/NTILE)   // 256
#define MAXDJ 8                 // gamma^513 ~ 8.6e-8 << 1e-3 tolerance

// proj smem (floats): x [64][132-layout], W [128][132-layout]
#define PROJ_SMEM_FLOATS (64*132 + 128*132)   // 25344 floats = 101,376 B -> 2 CTAs/SM

// attention smem (floats)
#define OFF_Q2   0                       // [64] rows x 256 k, pitch 260
#define OFF_K2   (OFF_Q2 + 64*260)       // 16640
#define OFF_VT   (OFF_K2 + 64*260)       // 33280 : V^T [128][64k] pitch 68
#define OFF_S2   (OFF_VT + 128*68)       // 41984 : S [64][64k] pitch 68
#define OFF_DEC  (OFF_S2 + 64*68)        // 46336
#define ATT_SMEM_FLOATS (OFF_DEC + 640)  // 46976 floats = 187,904 B

// ---------------- scratch ----------------
__device__ __align__(16) float g_cos[S*F];
__device__ __align__(16) float g_sin[S*F];
__device__ __align__(16) float g_qc[B*S*F];
__device__ __align__(16) float g_qs[B*S*F];
__device__ __align__(16) float g_kc[B*S*F];
__device__ __align__(16) float g_ks[B*S*F];
__device__ __align__(16) float g_v [B*S*F];

// ---------------- helpers ----------------
__device__ __forceinline__ uint32_t f2tf32(float f) {
    uint32_t r; asm("cvt.rna.tf32.f32 %0, %1;" : "=r"(r) : "f"(f)); return r;
}
__device__ __forceinline__ void mma_tf32(float c[4],
                                         uint32_t a0, uint32_t a1, uint32_t a2, uint32_t a3,
                                         uint32_t b0, uint32_t b1) {
    asm volatile("mma.sync.aligned.m16n8k8.row.col.f32.tf32.tf32.f32 "
                 "{%0,%1,%2,%3}, {%4,%5,%6,%7}, {%8,%9}, {%0,%1,%2,%3};"
                 : "+f"(c[0]), "+f"(c[1]), "+f"(c[2]), "+f"(c[3])
                 : "r"(a0), "r"(a1), "r"(a2), "r"(a3), "r"(b0), "r"(b1));
}

// permuted K-dim layouts: fragment float4 loads, conflict-free banks
// 256 k-cols, pitch 260 (score Q/K operands)
__device__ __forceinline__ int qkw(int r, int k) {
    int c = k & 7, kk = k >> 3;
    return r*260 + c*32 + (kk ^ ((c & 3) << 3));
}
// 64 k-cols, pitch 68 (S tile and V^T)
__device__ __forceinline__ int s2w(int r, int k) {
    int c = k & 7, kk = k >> 3;
    return r*68 + c*8 + (kk ^ (c & 4));
}
// 128 k-cols, pitch 132 (proj x/W operands)
__device__ __forceinline__ int pw(int r, int k) {
    int c = k & 7, kk = k >> 3;
    return r*132 + c*16 + (kk ^ (((c >> 1) & 1) << 3));
}

// ---------------- init: cos/sin tables ----------------
__global__ void init_tables(const float* __restrict__ theta) {
    int bx = blockIdx.x, t = threadIdx.x;
    float mt = (float)(bx + 1) * theta[t];
    float sn, cs;
    sincosf(mt, &sn, &cs);
    g_cos[bx*F + t] = cs;
    g_sin[bx*F + t] = sn;
}

// ---------------- QKV projection via mma.sync tf32 ----------------
__global__ void __launch_bounds__(256)
proj_mma_kernel(const float* __restrict__ x,
                const float* __restrict__ Wq, const float* __restrict__ bq,
                const float* __restrict__ Wk, const float* __restrict__ bk,
                const float* __restrict__ Wv, const float* __restrict__ bv) {
    extern __shared__ float sm[];
    uint32_t* xsu = (uint32_t*)sm;             // [64][132-layout]
    uint32_t* Wsu = (uint32_t*)(sm + 64*132);  // [128][132-layout]

    const int tid  = threadIdx.x;
    const int row0 = blockIdx.x * 64;

    // fill x tile (tf32-rounded, permuted layout)
    for (int idx = tid; idx < 64*32; idx += TPB) {
        int r  = idx >> 5;
        int k4 = (idx & 31) << 2;
        float4 xv = *(const float4*)(x + (size_t)(row0 + r)*F + k4);
        xsu[pw(r, k4+0)] = f2tf32(xv.x);
        xsu[pw(r, k4+1)] = f2tf32(xv.y);
        xsu[pw(r, k4+2)] = f2tf32(xv.z);
        xsu[pw(r, k4+3)] = f2tf32(xv.w);
    }

    const int w    = tid >> 5;
    const int lane = tid & 31;
    const int g    = lane >> 2;
    const int ti   = lane & 3;
    const int rw   = (w & 1) * 32;        // warp row base within 64
    const int cwb  = (w >> 1) * 32;       // warp col base within 128

    #pragma unroll 1
    for (int m = 0; m < 3; m++) {
        const float* Wm   = (m == 0) ? Wq : ((m == 1) ? Wk : Wv);
        const float* bias = (m == 0) ? bq : ((m == 1) ? bk : bv);

        __syncthreads();
        for (int idx = tid; idx < 128*32; idx += TPB) {
            int r  = idx >> 5;
            int k4 = (idx & 31) << 2;
            float4 wv = *(const float4*)(Wm + (size_t)r*F + k4);
            Wsu[pw(r, k4+0)] = f2tf32(wv.x);
            Wsu[pw(r, k4+1)] = f2tf32(wv.y);
            Wsu[pw(r, k4+2)] = f2tf32(wv.z);
            Wsu[pw(r, k4+3)] = f2tf32(wv.w);
        }
        __syncthreads();

        float acc[2][4][4];
        #pragma unroll
        for (int rb = 0; rb < 2; rb++)
            #pragma unroll
            for (int jn = 0; jn < 4; jn++)
                #pragma unroll
                for (int q = 0; q < 4; q++) acc[rb][jn][q] = 0.f;

        #pragma unroll
        for (int kk4 = 0; kk4 < 4; kk4++) {
            const int kbase = kk4 * 32;
            uint4 av[2][4];
            #pragma unroll
            for (int rb = 0; rb < 2; rb++) {
                const int rr = rw + rb*16;
                av[rb][0] = *(const uint4*)(xsu + pw(rr + g,     kbase + ti));
                av[rb][1] = *(const uint4*)(xsu + pw(rr + g + 8, kbase + ti));
                av[rb][2] = *(const uint4*)(xsu + pw(rr + g,     kbase + ti + 4));
                av[rb][3] = *(const uint4*)(xsu + pw(rr + g + 8, kbase + ti + 4));
            }
            #pragma unroll
            for (int jn = 0; jn < 4; jn++) {
                const int nr = cwb + jn*8 + g;
                uint4 b0 = *(const uint4*)(Wsu + pw(nr, kbase + ti));
                uint4 b1 = *(const uint4*)(Wsu + pw(nr, kbase + ti + 4));
                const uint32_t* b0p = (const uint32_t*)&b0;
                const uint32_t* b1p = (const uint32_t*)&b1;
                #pragma unroll
                for (int rb = 0; rb < 2; rb++) {
                    const uint32_t* a0p = (const uint32_t*)&av[rb][0];
                    const uint32_t* a1p = (const uint32_t*)&av[rb][1];
                    const uint32_t* a2p = (const uint32_t*)&av[rb][2];
                    const uint32_t* a3p = (const uint32_t*)&av[rb][3];
                    #pragma unroll
                    for (int l = 0; l < 4; l++)
                        mma_tf32(acc[rb][jn], a0p[l], a1p[l], a2p[l], a3p[l], b0p[l], b1p[l]);
                }
            }
        }

        // epilogue: bias (+ cos/sin modulation for q,k)
        float* gc = (m == 0) ? g_qc : g_kc;
        float* gs = (m == 0) ? g_qs : g_ks;
        #pragma unroll
        for (int jn = 0; jn < 4; jn++) {
            const int col = cwb + jn*8 + 2*ti;
            const float2 bb = *(const float2*)(bias + col);
            #pragma unroll
            for (int rb = 0; rb < 2; rb++) {
                #pragma unroll
                for (int h = 0; h < 2; h++) {
                    const int rowg = row0 + rw + rb*16 + g + 8*h;
                    const int srow = rowg & (S - 1);
                    float c0 = acc[rb][jn][2*h    ] + bb.x;
                    float c1 = acc[rb][jn][2*h + 1] + bb.y;
                    if (m < 2) {
                        float2 cv = *(const float2*)(g_cos + (size_t)srow*F + col);
                        float2 sv = *(const float2*)(g_sin + (size_t)srow*F + col);
                        *(float2*)(gc + (size_t)rowg*F + col) = make_float2(c0*cv.x, c1*cv.y);
                        *(float2*)(gs + (size_t)rowg*F + col) = make_float2(c0*sv.x, c1*sv.y);
                    } else {
                        *(float2*)(g_v + (size_t)rowg*F + col) = make_float2(c0, c1);
                    }
                }
            }
        }
    }
}

// ================= banded attention via mma.sync tf32 (vectorized frags) =================
__global__ void __launch_bounds__(256)
attn_mma_kernel(float* __restrict__ out) {
    extern __shared__ float sm[];
    uint32_t* Q2u = (uint32_t*)(sm + OFF_Q2);
    uint32_t* K2u = (uint32_t*)(sm + OFF_K2);
    uint32_t* VTu = (uint32_t*)(sm + OFF_VT);
    uint32_t* S2u = (uint32_t*)(sm + OFF_S2);
    float*    dec = sm + OFF_DEC;

    const int tid = threadIdx.x;
    // heavy-tile-first mapping
    const int i   = 63 - (blockIdx.x >> 2);
    const int b   = blockIdx.x & 3;
    const size_t qrow0 = (size_t)b * S + (size_t)i * 64;
    const float L = log2f(GAMMA);

    for (int e = tid; e < 640; e += TPB) dec[e] = exp2f((float)e * L);

    // Q2 fill (tf32-rounded, permuted)
    for (int idx = tid; idx < 64*32; idx += TPB) {
        int r  = idx >> 5;
        int k4 = (idx & 31) << 2;
        float4 a = *(const float4*)(g_qc + (qrow0 + r)*F + k4);
        Q2u[qkw(r, k4+0)] = f2tf32(a.x);
        Q2u[qkw(r, k4+1)] = f2tf32(a.y);
        Q2u[qkw(r, k4+2)] = f2tf32(a.z);
        Q2u[qkw(r, k4+3)] = f2tf32(a.w);
        float4 s = *(const float4*)(g_qs + (qrow0 + r)*F + k4);
        Q2u[qkw(r, 128+k4+0)] = f2tf32(s.x);
        Q2u[qkw(r, 128+k4+1)] = f2tf32(s.y);
        Q2u[qkw(r, 128+k4+2)] = f2tf32(s.z);
        Q2u[qkw(r, 128+k4+3)] = f2tf32(s.w);
    }

    const int w    = tid >> 5;
    const int lane = tid & 31;
    const int g    = lane >> 2;
    const int ti   = lane & 3;
    const int rw   = (w & 3) * 16;
    const int cw   = (w >> 2);

    float oc[8][4];
    #pragma unroll
    for (int jn = 0; jn < 8; jn++)
        #pragma unroll
        for (int q = 0; q < 4; q++) oc[jn][q] = 0.f;

    const int jmin = (i > MAXDJ) ? (i - MAXDJ) : 0;
    for (int j = i; j >= jmin; j--) {
        __syncthreads();
        const size_t krow0 = (size_t)b * S + (size_t)j * 64;

        // fill K2 (kc|ks) and VT (V transposed), tf32-rounded, permuted
        for (int idx = tid; idx < 64*32; idx += TPB) {
            int r  = idx >> 5;
            int k4 = (idx & 31) << 2;
            float4 a = *(const float4*)(g_kc + (krow0 + r)*F + k4);
            K2u[qkw(r, k4+0)] = f2tf32(a.x);
            K2u[qkw(r, k4+1)] = f2tf32(a.y);
            K2u[qkw(r, k4+2)] = f2tf32(a.z);
            K2u[qkw(r, k4+3)] = f2tf32(a.w);
            float4 s = *(const float4*)(g_ks + (krow0 + r)*F + k4);
            K2u[qkw(r, 128+k4+0)] = f2tf32(s.x);
            K2u[qkw(r, 128+k4+1)] = f2tf32(s.y);
            K2u[qkw(r, 128+k4+2)] = f2tf32(s.z);
            K2u[qkw(r, 128+k4+3)] = f2tf32(s.w);
            float4 v = *(const float4*)(g_v + (krow0 + r)*F + k4);
            VTu[s2w(k4+0, r)] = f2tf32(v.x);
            VTu[s2w(k4+1, r)] = f2tf32(v.y);
            VTu[s2w(k4+2, r)] = f2tf32(v.z);
            VTu[s2w(k4+3, r)] = f2tf32(v.w);
        }
        __syncthreads();

        // ---- score GEMM: warp tile 16x32, K=256, vectorized frags ----
        float sc[4][4];
        #pragma unroll
        for (int jn = 0; jn < 4; jn++)
            #pragma unroll
            for (int q = 0; q < 4; q++) sc[jn][q] = 0.f;

        #pragma unroll
        for (int kk4 = 0; kk4 < 8; kk4++) {
            const int kbase = kk4 * 32;
            uint4 a0v = *(const uint4*)(Q2u + qkw(rw + g,     kbase + ti));
            uint4 a1v = *(const uint4*)(Q2u + qkw(rw + g + 8, kbase + ti));
            uint4 a2v = *(const uint4*)(Q2u + qkw(rw + g,     kbase + ti + 4));
            uint4 a3v = *(const uint4*)(Q2u + qkw(rw + g + 8, kbase + ti + 4));
            const uint32_t* a0p = (const uint32_t*)&a0v;
            const uint32_t* a1p = (const uint32_t*)&a1v;
            const uint32_t* a2p = (const uint32_t*)&a2v;
            const uint32_t* a3p = (const uint32_t*)&a3v;
            #pragma unroll
            for (int jn = 0; jn < 4; jn++) {
                const int nrow = cw*32 + jn*8 + g;
                uint4 b0v = *(const uint4*)(K2u + qkw(nrow, kbase + ti));
                uint4 b1v = *(const uint4*)(K2u + qkw(nrow, kbase + ti + 4));
                const uint32_t* b0p = (const uint32_t*)&b0v;
                const uint32_t* b1p = (const uint32_t*)&b1v;
                #pragma unroll
                for (int l = 0; l < 4; l++)
                    mma_tf32(sc[jn], a0p[l], a1p[l], a2p[l], a3p[l], b0p[l], b1p[l]);
            }
        }

        // ---- epilogue: decay + causal mask, tf32 round, store S (permuted) ----
        {
            const int dj = (i - j) * 64;
            #pragma unroll
            for (int jn = 0; jn < 4; jn++) {
                const int col = cw*32 + jn*8 + 2*ti;
                const int rm0 = rw + g, rm1 = rw + g + 8;
                int e00 = dj + rm0 - col;
                int e01 = e00 - 1;
                int e10 = dj + rm1 - col;
                int e11 = e10 - 1;
                float d00 = (e00 >= 0) ? dec[e00] : 0.f;
                float d01 = (e01 >= 0) ? dec[e01] : 0.f;
                float d10 = (e10 >= 0) ? dec[e10] : 0.f;
                float d11 = (e11 >= 0) ? dec[e11] : 0.f;
                S2u[s2w(rm0, col    )] = f2tf32(sc[jn][0] * d00);
                S2u[s2w(rm0, col + 1)] = f2tf32(sc[jn][1] * d01);
                S2u[s2w(rm1, col    )] = f2tf32(sc[jn][2] * d10);
                S2u[s2w(rm1, col + 1)] = f2tf32(sc[jn][3] * d11);
            }
        }
        __syncthreads();

        // ---- O += S @ V: warp tile 16x64, K=64, vectorized frags ----
        #pragma unroll
        for (int kk4 = 0; kk4 < 2; kk4++) {
            const int kbase = kk4 * 32;
            uint4 a0v = *(const uint4*)(S2u + s2w(rw + g,     kbase + ti));
            uint4 a1v = *(const uint4*)(S2u + s2w(rw + g + 8, kbase + ti));
            uint4 a2v = *(const uint4*)(S2u + s2w(rw + g,     kbase + ti + 4));
            uint4 a3v = *(const uint4*)(S2u + s2w(rw + g + 8, kbase + ti + 4));
            const uint32_t* a0p = (const uint32_t*)&a0v;
            const uint32_t* a1p = (const uint32_t*)&a1v;
            const uint32_t* a2p = (const uint32_t*)&a2v;
            const uint32_t* a3p = (const uint32_t*)&a3v;
            #pragma unroll
            for (int jn = 0; jn < 8; jn++) {
                const int nc = cw*64 + jn*8 + g;
                uint4 b0v = *(const uint4*)(VTu + s2w(nc, kbase + ti));
                uint4 b1v = *(const uint4*)(VTu + s2w(nc, kbase + ti + 4));
                const uint32_t* b0p = (const uint32_t*)&b0v;
                const uint32_t* b1p = (const uint32_t*)&b1v;
                #pragma unroll
                for (int l = 0; l < 4; l++)
                    mma_tf32(oc[jn], a0p[l], a1p[l], a2p[l], a3p[l], b0p[l], b1p[l]);
            }
        }
    }

    // write O
    {
        const size_t row0 = qrow0 + rw + g;
        const size_t row1 = row0 + 8;
        #pragma unroll
        for (int jn = 0; jn < 8; jn++) {
            const int col = cw*64 + jn*8 + 2*ti;
            *(float2*)(out + row0*F + col) = make_float2(oc[jn][0], oc[jn][1]);
            *(float2*)(out + row1*F + col) = make_float2(oc[jn][2], oc[jn][3]);
        }
    }
}

// ---------------- launch ----------------
extern "C" void kernel_launch(void* const* d_in, const int* in_sizes, int n_in,
                              void* d_out, int out_size) {
    const float* x  = (const float*)d_in[0];
    const float* Wq = (const float*)d_in[1];
    const float* bq = (const float*)d_in[2];
    const float* Wk = (const float*)d_in[3];
    const float* bk = (const float*)d_in[4];
    const float* Wv = (const float*)d_in[5];
    const float* bv = (const float*)d_in[6];
    const float* th = (const float*)d_in[7];
    float* out = (float*)d_out;

    const size_t PROJ_SMEM = (size_t)PROJ_SMEM_FLOATS * sizeof(float);   // 101,376 B
    const size_t ATT_SMEM  = (size_t)ATT_SMEM_FLOATS * sizeof(float);    // 187,904 B

    cudaFuncSetAttribute(proj_mma_kernel, cudaFuncAttributeMaxDynamicSharedMemorySize, (int)PROJ_SMEM);
    cudaFuncSetAttribute(attn_mma_kernel, cudaFuncAttributeMaxDynamicSharedMemorySize, (int)ATT_SMEM);

    init_tables<<<S, F>>>(th);
    proj_mma_kernel<<<NQTILES, TPB, PROJ_SMEM>>>(x, Wq, bq, Wk, bk, Wv, bv);
    attn_mma_kernel<<<NQTILES, TPB, ATT_SMEM>>>(out);
}

// round 15
// speedup vs baseline: 1.0033x; 1.0033x over previous
#include <cuda_runtime.h>
#include <math.h>
#include <stdint.h>

#define B 4
#define S 4096
#define F 128
#define GAMMA 0.96875f
#define NTILE 64
#define TPB 256
#define NQTILES ((B*S)/NTILE)   // 256
#define MAXDJ 8                 // gamma^513 ~ 8.6e-8 << 1e-3 tolerance

// proj smem (floats): x [64][132-layout], W [128][132-layout]
#define PROJ_SMEM_FLOATS (64*132 + 128*132)   // 25344 floats = 101,376 B -> 2 CTAs/SM

// attention smem (floats)
#define OFF_Q2   0                       // [64] rows x 256 k, pitch 260
#define OFF_K2   (OFF_Q2 + 64*260)       // 16640
#define OFF_VT   (OFF_K2 + 64*260)       // 33280 : V^T [128][64k] pitch 68
#define OFF_S2   (OFF_VT + 128*68)       // 41984 : S [64][64k] pitch 68
#define OFF_DEC  (OFF_S2 + 64*68)        // 46336
#define ATT_SMEM_FLOATS (OFF_DEC + 640)  // 46976 floats = 187,904 B

// ---------------- scratch ----------------
__device__ __align__(16) float g_cos[S*F];
__device__ __align__(16) float g_sin[S*F];
__device__ __align__(16) float g_qc[B*S*F];
__device__ __align__(16) float g_qs[B*S*F];
__device__ __align__(16) float g_kc[B*S*F];
__device__ __align__(16) float g_ks[B*S*F];
__device__ __align__(16) float g_v [B*S*F];

// ---------------- helpers ----------------
__device__ __forceinline__ uint32_t f2tf32(float f) {
    uint32_t r; asm("cvt.rna.tf32.f32 %0, %1;" : "=r"(r) : "f"(f)); return r;
}
__device__ __forceinline__ void mma_tf32(float c[4],
                                         uint32_t a0, uint32_t a1, uint32_t a2, uint32_t a3,
                                         uint32_t b0, uint32_t b1) {
    asm volatile("mma.sync.aligned.m16n8k8.row.col.f32.tf32.tf32.f32 "
                 "{%0,%1,%2,%3}, {%4,%5,%6,%7}, {%8,%9}, {%0,%1,%2,%3};"
                 : "+f"(c[0]), "+f"(c[1]), "+f"(c[2]), "+f"(c[3])
                 : "r"(a0), "r"(a1), "r"(a2), "r"(a3), "r"(b0), "r"(b1));
}

// permuted K-dim layouts: fragment float4 loads, conflict-free banks
// 256 k-cols, pitch 260 (score Q/K operands)
__device__ __forceinline__ int qkw(int r, int k) {
    int c = k & 7, kk = k >> 3;
    return r*260 + c*32 + (kk ^ ((c & 3) << 3));
}
// 64 k-cols, pitch 68 (S tile and V^T)
__device__ __forceinline__ int s2w(int r, int k) {
    int c = k & 7, kk = k >> 3;
    return r*68 + c*8 + (kk ^ (c & 4));
}
// 128 k-cols, pitch 132 (proj x/W operands)
__device__ __forceinline__ int pw(int r, int k) {
    int c = k & 7, kk = k >> 3;
    return r*132 + c*16 + (kk ^ (((c >> 1) & 1) << 3));
}

// ---------------- init: cos/sin tables ----------------
__global__ void init_tables(const float* __restrict__ theta) {
    int bx = blockIdx.x, t = threadIdx.x;
    float mt = (float)(bx + 1) * theta[t];
    float sn, cs;
    sincosf(mt, &sn, &cs);
    g_cos[bx*F + t] = cs;
    g_sin[bx*F + t] = sn;
}

// ---------------- QKV projection via mma.sync tf32 ----------------
__global__ void __launch_bounds__(256)
proj_mma_kernel(const float* __restrict__ x,
                const float* __restrict__ Wq, const float* __restrict__ bq,
                const float* __restrict__ Wk, const float* __restrict__ bk,
                const float* __restrict__ Wv, const float* __restrict__ bv) {
    extern __shared__ float sm[];
    uint32_t* xsu = (uint32_t*)sm;             // [64][132-layout]
    uint32_t* Wsu = (uint32_t*)(sm + 64*132);  // [128][132-layout]

    const int tid  = threadIdx.x;
    const int row0 = blockIdx.x * 64;

    // fill x tile (tf32-rounded, permuted layout)
    for (int idx = tid; idx < 64*32; idx += TPB) {
        int r  = idx >> 5;
        int k4 = (idx & 31) << 2;
        float4 xv = *(const float4*)(x + (size_t)(row0 + r)*F + k4);
        xsu[pw(r, k4+0)] = f2tf32(xv.x);
        xsu[pw(r, k4+1)] = f2tf32(xv.y);
        xsu[pw(r, k4+2)] = f2tf32(xv.z);
        xsu[pw(r, k4+3)] = f2tf32(xv.w);
    }

    const int w    = tid >> 5;
    const int lane = tid & 31;
    const int g    = lane >> 2;
    const int ti   = lane & 3;
    const int rw   = (w & 1) * 32;        // warp row base within 64
    const int cwb  = (w >> 1) * 32;       // warp col base within 128

    #pragma unroll 1
    for (int m = 0; m < 3; m++) {
        const float* Wm   = (m == 0) ? Wq : ((m == 1) ? Wk : Wv);
        const float* bias = (m == 0) ? bq : ((m == 1) ? bk : bv);

        __syncthreads();
        for (int idx = tid; idx < 128*32; idx += TPB) {
            int r  = idx >> 5;
            int k4 = (idx & 31) << 2;
            float4 wv = *(const float4*)(Wm + (size_t)r*F + k4);
            Wsu[pw(r, k4+0)] = f2tf32(wv.x);
            Wsu[pw(r, k4+1)] = f2tf32(wv.y);
            Wsu[pw(r, k4+2)] = f2tf32(wv.z);
            Wsu[pw(r, k4+3)] = f2tf32(wv.w);
        }
        __syncthreads();

        float acc[2][4][4];
        #pragma unroll
        for (int rb = 0; rb < 2; rb++)
            #pragma unroll
            for (int jn = 0; jn < 4; jn++)
                #pragma unroll
                for (int q = 0; q < 4; q++) acc[rb][jn][q] = 0.f;

        #pragma unroll
        for (int kk4 = 0; kk4 < 4; kk4++) {
            const int kbase = kk4 * 32;
            uint4 av[2][4];
            #pragma unroll
            for (int rb = 0; rb < 2; rb++) {
                const int rr = rw + rb*16;
                av[rb][0] = *(const uint4*)(xsu + pw(rr + g,     kbase + ti));
                av[rb][1] = *(const uint4*)(xsu + pw(rr + g + 8, kbase + ti));
                av[rb][2] = *(const uint4*)(xsu + pw(rr + g,     kbase + ti + 4));
                av[rb][3] = *(const uint4*)(xsu + pw(rr + g + 8, kbase + ti + 4));
            }
            #pragma unroll
            for (int jn = 0; jn < 4; jn++) {
                const int nr = cwb + jn*8 + g;
                uint4 b0 = *(const uint4*)(Wsu + pw(nr, kbase + ti));
                uint4 b1 = *(const uint4*)(Wsu + pw(nr, kbase + ti + 4));
                const uint32_t* b0p = (const uint32_t*)&b0;
                const uint32_t* b1p = (const uint32_t*)&b1;
                #pragma unroll
                for (int rb = 0; rb < 2; rb++) {
                    const uint32_t* a0p = (const uint32_t*)&av[rb][0];
                    const uint32_t* a1p = (const uint32_t*)&av[rb][1];
                    const uint32_t* a2p = (const uint32_t*)&av[rb][2];
                    const uint32_t* a3p = (const uint32_t*)&av[rb][3];
                    #pragma unroll
                    for (int l = 0; l < 4; l++)
                        mma_tf32(acc[rb][jn], a0p[l], a1p[l], a2p[l], a3p[l], b0p[l], b1p[l]);
                }
            }
        }

        // epilogue: bias (+ cos/sin modulation for q,k)
        float* gc = (m == 0) ? g_qc : g_kc;
        float* gs = (m == 0) ? g_qs : g_ks;
        #pragma unroll
        for (int jn = 0; jn < 4; jn++) {
            const int col = cwb + jn*8 + 2*ti;
            const float2 bb = *(const float2*)(bias + col);
            #pragma unroll
            for (int rb = 0; rb < 2; rb++) {
                #pragma unroll
                for (int h = 0; h < 2; h++) {
                    const int rowg = row0 + rw + rb*16 + g + 8*h;
                    const int srow = rowg & (S - 1);
                    float c0 = acc[rb][jn][2*h    ] + bb.x;
                    float c1 = acc[rb][jn][2*h + 1] + bb.y;
                    if (m < 2) {
                        float2 cv = *(const float2*)(g_cos + (size_t)srow*F + col);
                        float2 sv = *(const float2*)(g_sin + (size_t)srow*F + col);
                        *(float2*)(gc + (size_t)rowg*F + col) = make_float2(c0*cv.x, c1*cv.y);
                        *(float2*)(gs + (size_t)rowg*F + col) = make_float2(c0*sv.x, c1*sv.y);
                    } else {
                        *(float2*)(g_v + (size_t)rowg*F + col) = make_float2(c0, c1);
                    }
                }
            }
        }
    }
}

// ================= banded attention via mma.sync tf32 (vectorized frags) =================
__global__ void __launch_bounds__(256)
attn_mma_kernel(float* __restrict__ out) {
    extern __shared__ float sm[];
    uint32_t* Q2u = (uint32_t*)(sm + OFF_Q2);
    uint32_t* K2u = (uint32_t*)(sm + OFF_K2);
    uint32_t* VTu = (uint32_t*)(sm + OFF_VT);
    uint32_t* S2u = (uint32_t*)(sm + OFF_S2);
    float*    dec = sm + OFF_DEC;

    const int tid = threadIdx.x;
    // heavy-tile-first mapping
    const int i   = 63 - (blockIdx.x >> 2);
    const int b   = blockIdx.x & 3;
    const size_t qrow0 = (size_t)b * S + (size_t)i * 64;
    const float L = log2f(GAMMA);

    for (int e = tid; e < 640; e += TPB) dec[e] = exp2f((float)e * L);

    // Q2 fill (tf32-rounded, permuted)
    for (int idx = tid; idx < 64*32; idx += TPB) {
        int r  = idx >> 5;
        int k4 = (idx & 31) << 2;
        float4 a = *(const float4*)(g_qc + (qrow0 + r)*F + k4);
        Q2u[qkw(r, k4+0)] = f2tf32(a.x);
        Q2u[qkw(r, k4+1)] = f2tf32(a.y);
        Q2u[qkw(r, k4+2)] = f2tf32(a.z);
        Q2u[qkw(r, k4+3)] = f2tf32(a.w);
        float4 s = *(const float4*)(g_qs + (qrow0 + r)*F + k4);
        Q2u[qkw(r, 128+k4+0)] = f2tf32(s.x);
        Q2u[qkw(r, 128+k4+1)] = f2tf32(s.y);
        Q2u[qkw(r, 128+k4+2)] = f2tf32(s.z);
        Q2u[qkw(r, 128+k4+3)] = f2tf32(s.w);
    }

    const int w    = tid >> 5;
    const int lane = tid & 31;
    const int g    = lane >> 2;
    const int ti   = lane & 3;
    const int rw   = (w & 3) * 16;
    const int cw   = (w >> 2);

    float oc[8][4];
    #pragma unroll
    for (int jn = 0; jn < 8; jn++)
        #pragma unroll
        for (int q = 0; q < 4; q++) oc[jn][q] = 0.f;

    const int jmin = (i > MAXDJ) ? (i - MAXDJ) : 0;
    for (int j = i; j >= jmin; j--) {
        __syncthreads();
        const size_t krow0 = (size_t)b * S + (size_t)j * 64;

        // fill K2 (kc|ks) and VT (V transposed), tf32-rounded, permuted
        for (int idx = tid; idx < 64*32; idx += TPB) {
            int r  = idx >> 5;
            int k4 = (idx & 31) << 2;
            float4 a = *(const float4*)(g_kc + (krow0 + r)*F + k4);
            K2u[qkw(r, k4+0)] = f2tf32(a.x);
            K2u[qkw(r, k4+1)] = f2tf32(a.y);
            K2u[qkw(r, k4+2)] = f2tf32(a.z);
            K2u[qkw(r, k4+3)] = f2tf32(a.w);
            float4 s = *(const float4*)(g_ks + (krow0 + r)*F + k4);
            K2u[qkw(r, 128+k4+0)] = f2tf32(s.x);
            K2u[qkw(r, 128+k4+1)] = f2tf32(s.y);
            K2u[qkw(r, 128+k4+2)] = f2tf32(s.z);
            K2u[qkw(r, 128+k4+3)] = f2tf32(s.w);
            float4 v = *(const float4*)(g_v + (krow0 + r)*F + k4);
            VTu[s2w(k4+0, r)] = f2tf32(v.x);
            VTu[s2w(k4+1, r)] = f2tf32(v.y);
            VTu[s2w(k4+2, r)] = f2tf32(v.z);
            VTu[s2w(k4+3, r)] = f2tf32(v.w);
        }
        __syncthreads();

        // ---- score GEMM: warp tile 16x32, K=256, vectorized frags ----
        float sc[4][4];
        #pragma unroll
        for (int jn = 0; jn < 4; jn++)
            #pragma unroll
            for (int q = 0; q < 4; q++) sc[jn][q] = 0.f;

        #pragma unroll
        for (int kk4 = 0; kk4 < 8; kk4++) {
            const int kbase = kk4 * 32;
            uint4 a0v = *(const uint4*)(Q2u + qkw(rw + g,     kbase + ti));
            uint4 a1v = *(const uint4*)(Q2u + qkw(rw + g + 8, kbase + ti));
            uint4 a2v = *(const uint4*)(Q2u + qkw(rw + g,     kbase + ti + 4));
            uint4 a3v = *(const uint4*)(Q2u + qkw(rw + g + 8, kbase + ti + 4));
            const uint32_t* a0p = (const uint32_t*)&a0v;
            const uint32_t* a1p = (const uint32_t*)&a1v;
            const uint32_t* a2p = (const uint32_t*)&a2v;
            const uint32_t* a3p = (const uint32_t*)&a3v;
            #pragma unroll
            for (int jn = 0; jn < 4; jn++) {
                const int nrow = cw*32 + jn*8 + g;
                uint4 b0v = *(const uint4*)(K2u + qkw(nrow, kbase + ti));
                uint4 b1v = *(const uint4*)(K2u + qkw(nrow, kbase + ti + 4));
                const uint32_t* b0p = (const uint32_t*)&b0v;
                const uint32_t* b1p = (const uint32_t*)&b1v;
                #pragma unroll
                for (int l = 0; l < 4; l++)
                    mma_tf32(sc[jn], a0p[l], a1p[l], a2p[l], a3p[l], b0p[l], b1p[l]);
            }
        }

        // ---- epilogue: decay + causal mask, tf32 round, store S (permuted) ----
        {
            const int dj = (i - j) * 64;
            #pragma unroll
            for (int jn = 0; jn < 4; jn++) {
                const int col = cw*32 + jn*8 + 2*ti;
                const int rm0 = rw + g, rm1 = rw + g + 8;
                int e00 = dj + rm0 - col;
                int e01 = e00 - 1;
                int e10 = dj + rm1 - col;
                int e11 = e10 - 1;
                float d00 = (e00 >= 0) ? dec[e00] : 0.f;
                float d01 = (e01 >= 0) ? dec[e01] : 0.f;
                float d10 = (e10 >= 0) ? dec[e10] : 0.f;
                float d11 = (e11 >= 0) ? dec[e11] : 0.f;
                S2u[s2w(rm0, col    )] = f2tf32(sc[jn][0] * d00);
                S2u[s2w(rm0, col + 1)] = f2tf32(sc[jn][1] * d01);
                S2u[s2w(rm1, col    )] = f2tf32(sc[jn][2] * d10);
                S2u[s2w(rm1, col + 1)] = f2tf32(sc[jn][3] * d11);
            }
        }
        __syncthreads();

        // ---- O += S @ V: warp tile 16x64, K=64, vectorized frags ----
        #pragma unroll
        for (int kk4 = 0; kk4 < 2; kk4++) {
            const int kbase = kk4 * 32;
            uint4 a0v = *(const uint4*)(S2u + s2w(rw + g,     kbase + ti));
            uint4 a1v = *(const uint4*)(S2u + s2w(rw + g + 8, kbase + ti));
            uint4 a2v = *(const uint4*)(S2u + s2w(rw + g,     kbase + ti + 4));
            uint4 a3v = *(const uint4*)(S2u + s2w(rw + g + 8, kbase + ti + 4));
            const uint32_t* a0p = (const uint32_t*)&a0v;
            const uint32_t* a1p = (const uint32_t*)&a1v;
            const uint32_t* a2p = (const uint32_t*)&a2v;
            const uint32_t* a3p = (const uint32_t*)&a3v;
            #pragma unroll
            for (int jn = 0; jn < 8; jn++) {
                const int nc = cw*64 + jn*8 + g;
                uint4 b0v = *(const uint4*)(VTu + s2w(nc, kbase + ti));
                uint4 b1v = *(const uint4*)(VTu + s2w(nc, kbase + ti + 4));
                const uint32_t* b0p = (const uint32_t*)&b0v;
                const uint32_t* b1p = (const uint32_t*)&b1v;
                #pragma unroll
                for (int l = 0; l < 4; l++)
                    mma_tf32(oc[jn], a0p[l], a1p[l], a2p[l], a3p[l], b0p[l], b1p[l]);
            }
        }
    }

    // write O
    {
        const size_t row0 = qrow0 + rw + g;
        const size_t row1 = row0 + 8;
        #pragma unroll
        for (int jn = 0; jn < 8; jn++) {
            const int col = cw*64 + jn*8 + 2*ti;
            *(float2*)(out + row0*F + col) = make_float2(oc[jn][0], oc[jn][1]);
            *(float2*)(out + row1*F + col) = make_float2(oc[jn][2], oc[jn][3]);
        }
    }
}

// ---------------- launch ----------------
extern "C" void kernel_launch(void* const* d_in, const int* in_sizes, int n_in,
                              void* d_out, int out_size) {
    const float* x  = (const float*)d_in[0];
    const float* Wq = (const float*)d_in[1];
    const float* bq = (const float*)d_in[2];
    const float* Wk = (const float*)d_in[3];
    const float* bk = (const float*)d_in[4];
    const float* Wv = (const float*)d_in[5];
    const float* bv = (const float*)d_in[6];
    const float* th = (const float*)d_in[7];
    float* out = (float*)d_out;

    const size_t PROJ_SMEM = (size_t)PROJ_SMEM_FLOATS * sizeof(float);   // 101,376 B
    const size_t ATT_SMEM  = (size_t)ATT_SMEM_FLOATS * sizeof(float);    // 187,904 B

    cudaFuncSetAttribute(proj_mma_kernel, cudaFuncAttributeMaxDynamicSharedMemorySize, (int)PROJ_SMEM);
    cudaFuncSetAttribute(attn_mma_kernel, cudaFuncAttributeMaxDynamicSharedMemorySize, (int)ATT_SMEM);

    init_tables<<<S, F>>>(th);
    proj_mma_kernel<<<NQTILES, TPB, PROJ_SMEM>>>(x, Wq, bq, Wk, bk, Wv, bv);
    attn_mma_kernel<<<NQTILES, TPB, ATT_SMEM>>>(out);
}

// round 16
// speedup vs baseline: 1.0054x; 1.0021x over previous
#include <cuda_runtime.h>
#include <math.h>
#include <stdint.h>

#define B 4
#define S 4096
#define F 128
#define GAMMA 0.96875f
#define NTILE 64
#define TPB 256
#define NQTILES ((B*S)/NTILE)   // 256
#define MAXDJ 8                 // gamma^513 ~ 8.6e-8 << 1e-3 tolerance

// proj smem (floats): x [64][132-layout], W [128][132-layout]
#define PROJ_SMEM_FLOATS (64*132 + 128*132)   // 25344 floats = 101,376 B -> 2 CTAs/SM

// attention smem (floats)
#define OFF_Q2   0                       // [64] rows x 256 k, pitch 260
#define OFF_K2   (OFF_Q2 + 64*260)       // 16640
#define OFF_VT   (OFF_K2 + 64*260)       // 33280 : V^T [128][64k] pitch 68
#define OFF_S2   (OFF_VT + 128*68)       // 41984 : S [64][64k] pitch 68
#define OFF_DEC  (OFF_S2 + 64*68)        // 46336
#define ATT_SMEM_FLOATS (OFF_DEC + 640)  // 46976 floats = 187,904 B

// ---------------- scratch ----------------
__device__ __align__(16) float g_cos[S*F];
__device__ __align__(16) float g_sin[S*F];
__device__ __align__(16) float g_qc[B*S*F];
__device__ __align__(16) float g_qs[B*S*F];
__device__ __align__(16) float g_kc[B*S*F];
__device__ __align__(16) float g_ks[B*S*F];
__device__ __align__(16) float g_v [B*S*F];

// ---------------- helpers ----------------
__device__ __forceinline__ uint32_t f2tf32(float f) {
    uint32_t r; asm("cvt.rna.tf32.f32 %0, %1;" : "=r"(r) : "f"(f)); return r;
}
__device__ __forceinline__ void mma_tf32(float c[4],
                                         uint32_t a0, uint32_t a1, uint32_t a2, uint32_t a3,
                                         uint32_t b0, uint32_t b1) {
    asm volatile("mma.sync.aligned.m16n8k8.row.col.f32.tf32.tf32.f32 "
                 "{%0,%1,%2,%3}, {%4,%5,%6,%7}, {%8,%9}, {%0,%1,%2,%3};"
                 : "+f"(c[0]), "+f"(c[1]), "+f"(c[2]), "+f"(c[3])
                 : "r"(a0), "r"(a1), "r"(a2), "r"(a3), "r"(b0), "r"(b1));
}

// permuted K-dim layouts: fragment float4 loads, conflict-free banks
// 256 k-cols, pitch 260 (score Q/K operands)
__device__ __forceinline__ int qkw(int r, int k) {
    int c = k & 7, kk = k >> 3;
    return r*260 + c*32 + (kk ^ ((c & 3) << 3));
}
// 64 k-cols, pitch 68 (S tile and V^T)
__device__ __forceinline__ int s2w(int r, int k) {
    int c = k & 7, kk = k >> 3;
    return r*68 + c*8 + (kk ^ (c & 4));
}
// 128 k-cols, pitch 132 (proj x/W operands)
__device__ __forceinline__ int pw(int r, int k) {
    int c = k & 7, kk = k >> 3;
    return r*132 + c*16 + (kk ^ (((c >> 1) & 1) << 3));
}

// ---------------- init: cos/sin tables ----------------
__global__ void init_tables(const float* __restrict__ theta) {
    int bx = blockIdx.x, t = threadIdx.x;
    float mt = (float)(bx + 1) * theta[t];
    float sn, cs;
    sincosf(mt, &sn, &cs);
    g_cos[bx*F + t] = cs;
    g_sin[bx*F + t] = sn;
}

// ---------------- QKV projection via mma.sync tf32 ----------------
__global__ void __launch_bounds__(256)
proj_mma_kernel(const float* __restrict__ x,
                const float* __restrict__ Wq, const float* __restrict__ bq,
                const float* __restrict__ Wk, const float* __restrict__ bk,
                const float* __restrict__ Wv, const float* __restrict__ bv) {
    extern __shared__ float sm[];
    uint32_t* xsu = (uint32_t*)sm;             // [64][132-layout]
    uint32_t* Wsu = (uint32_t*)(sm + 64*132);  // [128][132-layout]

    const int tid  = threadIdx.x;
    const int row0 = blockIdx.x * 64;

    // fill x tile (tf32-rounded, permuted layout)
    for (int idx = tid; idx < 64*32; idx += TPB) {
        int r  = idx >> 5;
        int k4 = (idx & 31) << 2;
        float4 xv = *(const float4*)(x + (size_t)(row0 + r)*F + k4);
        xsu[pw(r, k4+0)] = f2tf32(xv.x);
        xsu[pw(r, k4+1)] = f2tf32(xv.y);
        xsu[pw(r, k4+2)] = f2tf32(xv.z);
        xsu[pw(r, k4+3)] = f2tf32(xv.w);
    }

    const int w    = tid >> 5;
    const int lane = tid & 31;
    const int g    = lane >> 2;
    const int ti   = lane & 3;
    const int rw   = (w & 1) * 32;        // warp row base within 64
    const int cwb  = (w >> 1) * 32;       // warp col base within 128

    #pragma unroll 1
    for (int m = 0; m < 3; m++) {
        const float* Wm   = (m == 0) ? Wq : ((m == 1) ? Wk : Wv);
        const float* bias = (m == 0) ? bq : ((m == 1) ? bk : bv);

        __syncthreads();
        for (int idx = tid; idx < 128*32; idx += TPB) {
            int r  = idx >> 5;
            int k4 = (idx & 31) << 2;
            float4 wv = *(const float4*)(Wm + (size_t)r*F + k4);
            Wsu[pw(r, k4+0)] = f2tf32(wv.x);
            Wsu[pw(r, k4+1)] = f2tf32(wv.y);
            Wsu[pw(r, k4+2)] = f2tf32(wv.z);
            Wsu[pw(r, k4+3)] = f2tf32(wv.w);
        }
        __syncthreads();

        float acc[2][4][4];
        #pragma unroll
        for (int rb = 0; rb < 2; rb++)
            #pragma unroll
            for (int jn = 0; jn < 4; jn++)
                #pragma unroll
                for (int q = 0; q < 4; q++) acc[rb][jn][q] = 0.f;

        #pragma unroll
        for (int kk4 = 0; kk4 < 4; kk4++) {
            const int kbase = kk4 * 32;
            uint4 av[2][4];
            #pragma unroll
            for (int rb = 0; rb < 2; rb++) {
                const int rr = rw + rb*16;
                av[rb][0] = *(const uint4*)(xsu + pw(rr + g,     kbase + ti));
                av[rb][1] = *(const uint4*)(xsu + pw(rr + g + 8, kbase + ti));
                av[rb][2] = *(const uint4*)(xsu + pw(rr + g,     kbase + ti + 4));
                av[rb][3] = *(const uint4*)(xsu + pw(rr + g + 8, kbase + ti + 4));
            }
            #pragma unroll
            for (int jn = 0; jn < 4; jn++) {
                const int nr = cwb + jn*8 + g;
                uint4 b0 = *(const uint4*)(Wsu + pw(nr, kbase + ti));
                uint4 b1 = *(const uint4*)(Wsu + pw(nr, kbase + ti + 4));
                const uint32_t* b0p = (const uint32_t*)&b0;
                const uint32_t* b1p = (const uint32_t*)&b1;
                #pragma unroll
                for (int rb = 0; rb < 2; rb++) {
                    const uint32_t* a0p = (const uint32_t*)&av[rb][0];
                    const uint32_t* a1p = (const uint32_t*)&av[rb][1];
                    const uint32_t* a2p = (const uint32_t*)&av[rb][2];
                    const uint32_t* a3p = (const uint32_t*)&av[rb][3];
                    #pragma unroll
                    for (int l = 0; l < 4; l++)
                        mma_tf32(acc[rb][jn], a0p[l], a1p[l], a2p[l], a3p[l], b0p[l], b1p[l]);
                }
            }
        }

        // epilogue: bias (+ cos/sin modulation for q,k)
        float* gc = (m == 0) ? g_qc : g_kc;
        float* gs = (m == 0) ? g_qs : g_ks;
        #pragma unroll
        for (int jn = 0; jn < 4; jn++) {
            const int col = cwb + jn*8 + 2*ti;
            const float2 bb = *(const float2*)(bias + col);
            #pragma unroll
            for (int rb = 0; rb < 2; rb++) {
                #pragma unroll
                for (int h = 0; h < 2; h++) {
                    const int rowg = row0 + rw + rb*16 + g + 8*h;
                    const int srow = rowg & (S - 1);
                    float c0 = acc[rb][jn][2*h    ] + bb.x;
                    float c1 = acc[rb][jn][2*h + 1] + bb.y;
                    if (m < 2) {
                        float2 cv = *(const float2*)(g_cos + (size_t)srow*F + col);
                        float2 sv = *(const float2*)(g_sin + (size_t)srow*F + col);
                        *(float2*)(gc + (size_t)rowg*F + col) = make_float2(c0*cv.x, c1*cv.y);
                        *(float2*)(gs + (size_t)rowg*F + col) = make_float2(c0*sv.x, c1*sv.y);
                    } else {
                        *(float2*)(g_v + (size_t)rowg*F + col) = make_float2(c0, c1);
                    }
                }
            }
        }
    }
}

// ================= banded attention via mma.sync tf32 (vectorized frags) =================
__global__ void __launch_bounds__(256)
attn_mma_kernel(float* __restrict__ out) {
    extern __shared__ float sm[];
    uint32_t* Q2u = (uint32_t*)(sm + OFF_Q2);
    uint32_t* K2u = (uint32_t*)(sm + OFF_K2);
    uint32_t* VTu = (uint32_t*)(sm + OFF_VT);
    uint32_t* S2u = (uint32_t*)(sm + OFF_S2);
    float*    dec = sm + OFF_DEC;

    const int tid = threadIdx.x;
    // heavy-tile-first mapping
    const int i   = 63 - (blockIdx.x >> 2);
    const int b   = blockIdx.x & 3;
    const size_t qrow0 = (size_t)b * S + (size_t)i * 64;
    const float L = log2f(GAMMA);

    for (int e = tid; e < 640; e += TPB) dec[e] = exp2f((float)e * L);

    // Q2 fill (tf32-rounded, permuted)
    for (int idx = tid; idx < 64*32; idx += TPB) {
        int r  = idx >> 5;
        int k4 = (idx & 31) << 2;
        float4 a = *(const float4*)(g_qc + (qrow0 + r)*F + k4);
        Q2u[qkw(r, k4+0)] = f2tf32(a.x);
        Q2u[qkw(r, k4+1)] = f2tf32(a.y);
        Q2u[qkw(r, k4+2)] = f2tf32(a.z);
        Q2u[qkw(r, k4+3)] = f2tf32(a.w);
        float4 s = *(const float4*)(g_qs + (qrow0 + r)*F + k4);
        Q2u[qkw(r, 128+k4+0)] = f2tf32(s.x);
        Q2u[qkw(r, 128+k4+1)] = f2tf32(s.y);
        Q2u[qkw(r, 128+k4+2)] = f2tf32(s.z);
        Q2u[qkw(r, 128+k4+3)] = f2tf32(s.w);
    }

    const int w    = tid >> 5;
    const int lane = tid & 31;
    const int g    = lane >> 2;
    const int ti   = lane & 3;
    const int rw   = (w & 3) * 16;
    const int cw   = (w >> 2);

    float oc[8][4];
    #pragma unroll
    for (int jn = 0; jn < 8; jn++)
        #pragma unroll
        for (int q = 0; q < 4; q++) oc[jn][q] = 0.f;

    const int jmin = (i > MAXDJ) ? (i - MAXDJ) : 0;
    for (int j = i; j >= jmin; j--) {
        __syncthreads();
        const size_t krow0 = (size_t)b * S + (size_t)j * 64;

        // fill K2 (kc|ks) and VT (V transposed), tf32-rounded, permuted
        for (int idx = tid; idx < 64*32; idx += TPB) {
            int r  = idx >> 5;
            int k4 = (idx & 31) << 2;
            float4 a = *(const float4*)(g_kc + (krow0 + r)*F + k4);
            K2u[qkw(r, k4+0)] = f2tf32(a.x);
            K2u[qkw(r, k4+1)] = f2tf32(a.y);
            K2u[qkw(r, k4+2)] = f2tf32(a.z);
            K2u[qkw(r, k4+3)] = f2tf32(a.w);
            float4 s = *(const float4*)(g_ks + (krow0 + r)*F + k4);
            K2u[qkw(r, 128+k4+0)] = f2tf32(s.x);
            K2u[qkw(r, 128+k4+1)] = f2tf32(s.y);
            K2u[qkw(r, 128+k4+2)] = f2tf32(s.z);
            K2u[qkw(r, 128+k4+3)] = f2tf32(s.w);
            float4 v = *(const float4*)(g_v + (krow0 + r)*F + k4);
            VTu[s2w(k4+0, r)] = f2tf32(v.x);
            VTu[s2w(k4+1, r)] = f2tf32(v.y);
            VTu[s2w(k4+2, r)] = f2tf32(v.z);
            VTu[s2w(k4+3, r)] = f2tf32(v.w);
        }
        __syncthreads();

        // ---- score GEMM: warp tile 16x32, K=256, vectorized frags ----
        float sc[4][4];
        #pragma unroll
        for (int jn = 0; jn < 4; jn++)
            #pragma unroll
            for (int q = 0; q < 4; q++) sc[jn][q] = 0.f;

        #pragma unroll
        for (int kk4 = 0; kk4 < 8; kk4++) {
            const int kbase = kk4 * 32;
            uint4 a0v = *(const uint4*)(Q2u + qkw(rw + g,     kbase + ti));
            uint4 a1v = *(const uint4*)(Q2u + qkw(rw + g + 8, kbase + ti));
            uint4 a2v = *(const uint4*)(Q2u + qkw(rw + g,     kbase + ti + 4));
            uint4 a3v = *(const uint4*)(Q2u + qkw(rw + g + 8, kbase + ti + 4));
            const uint32_t* a0p = (const uint32_t*)&a0v;
            const uint32_t* a1p = (const uint32_t*)&a1v;
            const uint32_t* a2p = (const uint32_t*)&a2v;
            const uint32_t* a3p = (const uint32_t*)&a3v;
            #pragma unroll
            for (int jn = 0; jn < 4; jn++) {
                const int nrow = cw*32 + jn*8 + g;
                uint4 b0v = *(const uint4*)(K2u + qkw(nrow, kbase + ti));
                uint4 b1v = *(const uint4*)(K2u + qkw(nrow, kbase + ti + 4));
                const uint32_t* b0p = (const uint32_t*)&b0v;
                const uint32_t* b1p = (const uint32_t*)&b1v;
                #pragma unroll
                for (int l = 0; l < 4; l++)
                    mma_tf32(sc[jn], a0p[l], a1p[l], a2p[l], a3p[l], b0p[l], b1p[l]);
            }
        }

        // ---- epilogue: decay + causal mask, tf32 round, store S (permuted) ----
        {
            const int dj = (i - j) * 64;
            #pragma unroll
            for (int jn = 0; jn < 4; jn++) {
                const int col = cw*32 + jn*8 + 2*ti;
                const int rm0 = rw + g, rm1 = rw + g + 8;
                int e00 = dj + rm0 - col;
                int e01 = e00 - 1;
                int e10 = dj + rm1 - col;
                int e11 = e10 - 1;
                float d00 = (e00 >= 0) ? dec[e00] : 0.f;
                float d01 = (e01 >= 0) ? dec[e01] : 0.f;
                float d10 = (e10 >= 0) ? dec[e10] : 0.f;
                float d11 = (e11 >= 0) ? dec[e11] : 0.f;
                S2u[s2w(rm0, col    )] = f2tf32(sc[jn][0] * d00);
                S2u[s2w(rm0, col + 1)] = f2tf32(sc[jn][1] * d01);
                S2u[s2w(rm1, col    )] = f2tf32(sc[jn][2] * d10);
                S2u[s2w(rm1, col + 1)] = f2tf32(sc[jn][3] * d11);
            }
        }
        __syncthreads();

        // ---- O += S @ V: warp tile 16x64, K=64, vectorized frags ----
        #pragma unroll
        for (int kk4 = 0; kk4 < 2; kk4++) {
            const int kbase = kk4 * 32;
            uint4 a0v = *(const uint4*)(S2u + s2w(rw + g,     kbase + ti));
            uint4 a1v = *(const uint4*)(S2u + s2w(rw + g + 8, kbase + ti));
            uint4 a2v = *(const uint4*)(S2u + s2w(rw + g,     kbase + ti + 4));
            uint4 a3v = *(const uint4*)(S2u + s2w(rw + g + 8, kbase + ti + 4));
            const uint32_t* a0p = (const uint32_t*)&a0v;
            const uint32_t* a1p = (const uint32_t*)&a1v;
            const uint32_t* a2p = (const uint32_t*)&a2v;
            const uint32_t* a3p = (const uint32_t*)&a3v;
            #pragma unroll
            for (int jn = 0; jn < 8; jn++) {
                const int nc = cw*64 + jn*8 + g;
                uint4 b0v = *(const uint4*)(VTu + s2w(nc, kbase + ti));
                uint4 b1v = *(const uint4*)(VTu + s2w(nc, kbase + ti + 4));
                const uint32_t* b0p = (const uint32_t*)&b0v;
                const uint32_t* b1p = (const uint32_t*)&b1v;
                #pragma unroll
                for (int l = 0; l < 4; l++)
                    mma_tf32(oc[jn], a0p[l], a1p[l], a2p[l], a3p[l], b0p[l], b1p[l]);
            }
        }
    }

    // write O
    {
        const size_t row0 = qrow0 + rw + g;
        const size_t row1 = row0 + 8;
        #pragma unroll
        for (int jn = 0; jn < 8; jn++) {
            const int col = cw*64 + jn*8 + 2*ti;
            *(float2*)(out + row0*F + col) = make_float2(oc[jn][0], oc[jn][1]);
            *(float2*)(out + row1*F + col) = make_float2(oc[jn][2], oc[jn][3]);
        }
    }
}

// ---------------- launch ----------------
extern "C" void kernel_launch(void* const* d_in, const int* in_sizes, int n_in,
                              void* d_out, int out_size) {
    const float* x  = (const float*)d_in[0];
    const float* Wq = (const float*)d_in[1];
    const float* bq = (const float*)d_in[2];
    const float* Wk = (const float*)d_in[3];
    const float* bk = (const float*)d_in[4];
    const float* Wv = (const float*)d_in[5];
    const float* bv = (const float*)d_in[6];
    const float* th = (const float*)d_in[7];
    float* out = (float*)d_out;

    const size_t PROJ_SMEM = (size_t)PROJ_SMEM_FLOATS * sizeof(float);   // 101,376 B
    const size_t ATT_SMEM  = (size_t)ATT_SMEM_FLOATS * sizeof(float);    // 187,904 B

    cudaFuncSetAttribute(proj_mma_kernel, cudaFuncAttributeMaxDynamicSharedMemorySize, (int)PROJ_SMEM);
    cudaFuncSetAttribute(attn_mma_kernel, cudaFuncAttributeMaxDynamicSharedMemorySize, (int)ATT_SMEM);

    init_tables<<<S, F>>>(th);
    proj_mma_kernel<<<NQTILES, TPB, PROJ_SMEM>>>(x, Wq, bq, Wk, bk, Wv, bv);
    attn_mma_kernel<<<NQTILES, TPB, ATT_SMEM>>>(out);
}